// round 10
// baseline (speedup 1.0000x reference)
#include <cuda_runtime.h>
#include <cuda_bf16.h>
#include <cstdint>

#define Bq 256      // queries
#define Dk 768      // feature dim
#define Nn 131072   // database rows
#define Lo 512      // output row length

// smem layout: per buffer, q hi/lo tiles 256x144B each, db hi/lo tiles 128x144B each
#define F_QH   0
#define F_QL   36864
#define F_DH   73728
#define F_DL   92160
#define F_BUF  110592
#define SM_INVN 221184          // 128 floats
#define SMEM_TOTAL 221824       // < 227 KB cap, 1 CTA/SM

__device__ __nv_bfloat16 g_qh[Bq * Dk];
__device__ __nv_bfloat16 g_ql[Bq * Dk];
__device__ unsigned long long g_best[Bq];

// ---------------- helpers ----------------
__device__ __forceinline__ uint32_t smem_u32(const void* p) {
    uint32_t a;
    asm("{ .reg .u64 t; cvta.to.shared.u64 t, %1; cvt.u32.u64 %0, t; }"
        : "=r"(a) : "l"(p));
    return a;
}
__device__ __forceinline__ unsigned long long pack_key(float v, unsigned idx) {
    unsigned u = __float_as_uint(v);
    u = (u & 0x80000000u) ? ~u : (u | 0x80000000u);
    return ((unsigned long long)u << 32) | (unsigned)(~idx);
}
__device__ __forceinline__ uint32_t b2u(__nv_bfloat162 h) {
    return *reinterpret_cast<uint32_t*>(&h);
}
__device__ __forceinline__ void ldsm_x4(uint32_t* r, uint32_t a) {
    asm volatile("ldmatrix.sync.aligned.m8n8.x4.shared.b16 {%0,%1,%2,%3}, [%4];"
                 : "=r"(r[0]), "=r"(r[1]), "=r"(r[2]), "=r"(r[3]) : "r"(a));
}
__device__ __forceinline__ void mma16816(float* d, const uint32_t* a, const uint32_t* b) {
    asm volatile(
        "mma.sync.aligned.m16n8k16.row.col.f32.bf16.bf16.f32 "
        "{%0,%1,%2,%3},{%4,%5,%6,%7},{%8,%9},{%0,%1,%2,%3};"
        : "+f"(d[0]), "+f"(d[1]), "+f"(d[2]), "+f"(d[3])
        : "r"(a[0]), "r"(a[1]), "r"(a[2]), "r"(a[3]), "r"(b[0]), "r"(b[1]));
}

// ---------------- convert queries (hi/lo split) + init ----------------
__global__ void convert_init_kernel(const float* __restrict__ x) {
    int i = blockIdx.x * 256 + threadIdx.x;
    float f = x[i];
    __nv_bfloat16 h = __float2bfloat16(f);
    g_qh[i] = h;
    g_ql[i] = __float2bfloat16(f - __bfloat162float(h));
    if (blockIdx.x == 0) g_best[threadIdx.x] = 0ull;
}

// ---------------- sim: bf16x3 exact GEMM, 256q x 128n per CTA, db read once ----
__global__ void __launch_bounds__(256, 1) sim_kernel(const float* __restrict__ db) {
    extern __shared__ char smem[];
    const uint32_t sb32 = smem_u32(smem);
    const int tid  = threadIdx.x;
    const int lane = tid & 31;
    const int w    = tid >> 5;
    const int n0   = blockIdx.x * 128;
    const int qb   = (w & 3) * 64;     // 64 queries per warp (mi covers 4x16)
    const int nb   = (w >> 2) * 64;    // 64 db rows per warp half
    float* s_invn  = (float*)(smem + SM_INVN);

    const int row  = tid >> 1;         // 0..127 (db row)
    const int half = tid & 1;

    float acc[4][8][4];
#pragma unroll
    for (int a = 0; a < 4; a++)
#pragma unroll
        for (int b = 0; b < 8; b++)
#pragma unroll
            for (int r = 0; r < 4; r++) acc[a][b][r] = 0.f;
    float ps = 0.f;

#pragma unroll 1
    for (int c = 0; c < 12; c++) {
        const int bufo = (c & 1) * F_BUF;
        char* buf = smem + bufo;
        const int k0 = c * 64;

        // ---- q tiles: 256 rows x 64k, hi and lo (precomputed bf16) ----
#pragma unroll
        for (int v = 0; v < 8; v++) {
            int ii  = tid + 256 * v;       // 0..2047
            int qr  = ii >> 3;             // 0..255
            int c16 = ii & 7;              // 8 x uint4 per row
            uint32_t soff = (uint32_t)(qr * 144 + c16 * 16);
            *(uint4*)(buf + F_QH + soff) =
                *(const uint4*)(g_qh + (size_t)qr * Dk + k0 + c16 * 8);
            *(uint4*)(buf + F_QL + soff) =
                *(const uint4*)(g_ql + (size_t)qr * Dk + k0 + c16 * 8);
        }
        // ---- db tile: 128 rows x 64k fp32 -> bf16 hi/lo, fuse norms ----
        {
            const float4* dsrc = (const float4*)(db + (size_t)(n0 + row) * Dk + k0 + half * 32);
            char* ph = buf + F_DH + row * 144 + half * 64;
            char* pl = buf + F_DL + row * 144 + half * 64;
#pragma unroll
            for (int i = 0; i < 8; i++) {
                float4 f = dsrc[i];
                ps = fmaf(f.x, f.x, fmaf(f.y, f.y, fmaf(f.z, f.z, fmaf(f.w, f.w, ps))));
                __nv_bfloat162 h01 = __floats2bfloat162_rn(f.x, f.y);
                __nv_bfloat162 h23 = __floats2bfloat162_rn(f.z, f.w);
                __nv_bfloat162 l01 = __floats2bfloat162_rn(f.x - __low2float(h01),
                                                           f.y - __high2float(h01));
                __nv_bfloat162 l23 = __floats2bfloat162_rn(f.z - __low2float(h23),
                                                           f.w - __high2float(h23));
                *(uint2*)(ph + i * 8) = make_uint2(b2u(h01), b2u(h23));
                *(uint2*)(pl + i * 8) = make_uint2(b2u(l01), b2u(l23));
            }
        }
        __syncthreads();

        const uint32_t sqh = sb32 + bufo + F_QH;
        const uint32_t sql = sb32 + bufo + F_QL;
        const uint32_t sdh = sb32 + bufo + F_DH;
        const uint32_t sdl = sb32 + bufo + F_DL;
#pragma unroll
        for (int ks = 0; ks < 4; ks++) {
            uint32_t aH[4][4], aL[4][4];
#pragma unroll
            for (int mi = 0; mi < 4; mi++) {
                uint32_t ao = (uint32_t)((qb + mi * 16 + (lane & 15)) * 144 +
                                         ks * 32 + (lane >> 4) * 16);
                ldsm_x4(aH[mi], sqh + ao);
                ldsm_x4(aL[mi], sql + ao);
            }
#pragma unroll
            for (int nip = 0; nip < 4; nip++) {
                uint32_t bo = (uint32_t)((nb + nip * 16 + (lane & 7) +
                                          ((lane >> 4) & 1) * 8) * 144 +
                                         ks * 32 + ((lane >> 3) & 1) * 16);
                uint32_t bh[4], bl[4];
                ldsm_x4(bh, sdh + bo);
                ldsm_x4(bl, sdl + bo);
#pragma unroll
                for (int mi = 0; mi < 4; mi++)
#pragma unroll
                    for (int s = 0; s < 2; s++) {
                        float* d = acc[mi][nip * 2 + s];
                        mma16816(d, aH[mi], &bh[2 * s]);   // xh * dh
                        mma16816(d, aL[mi], &bh[2 * s]);   // xl * dh
                        mma16816(d, aH[mi], &bl[2 * s]);   // xh * dl
                    }
            }
        }
        // no trailing sync: next chunk writes the other buffer; reuse of this
        // buffer at c+2 is ordered by the sync inside chunk c+1.
    }
    __syncthreads();   // all MMAs done

    // ---- inverse norms for this 128-row tile ----
    {
        float s = ps + __shfl_xor_sync(0xffffffffu, ps, 1);
        if (!half) s_invn[row] = 1.0f / fmaxf(sqrtf(s), 1e-8f);
    }
    __syncthreads();

    // ---- exact per-q argmax contribution: fold 16n, then atomicMax ----
#pragma unroll
    for (int mi = 0; mi < 4; mi++)
#pragma unroll
        for (int g8 = 0; g8 < 2; g8++) {
            const int q = qb + mi * 16 + g8 * 8 + (lane >> 2);
            unsigned long long b = 0ull;
#pragma unroll
            for (int ni = 0; ni < 8; ni++)
#pragma unroll
                for (int s = 0; s < 2; s++) {
                    int nl = nb + ni * 8 + (lane & 3) * 2 + s;
                    float v = acc[mi][ni][g8 * 2 + s] * s_invn[nl];
                    unsigned long long cand = pack_key(v, (unsigned)(n0 + nl));
                    b = (cand > b) ? cand : b;
                }
            unsigned long long o;
            o = __shfl_xor_sync(0xffffffffu, b, 1); b = (o > b) ? o : b;
            o = __shfl_xor_sync(0xffffffffu, b, 2); b = (o > b) ? o : b;
            if ((lane & 3) == 0) atomicMax(&g_best[q], b);
        }
}

// ---------------- gather ----------------
__global__ void gather_kernel(const float* __restrict__ y, float* __restrict__ out) {
    const int b = blockIdx.x;
    unsigned idx = ~((unsigned)(g_best[b] & 0xffffffffull));
    const float4* src = (const float4*)(y + (size_t)idx * Lo);
    float4* dst = (float4*)(out + (size_t)b * Lo);
    dst[threadIdx.x] = src[threadIdx.x];
}

extern "C" void kernel_launch(void* const* d_in, const int* in_sizes, int n_in,
                              void* d_out, int out_size) {
    const float* imu = (const float*)d_in[0];
    const float* dbx = (const float*)d_in[1];
    const float* dby = (const float*)d_in[2];
    float* out = (float*)d_out;

    cudaFuncSetAttribute(sim_kernel, cudaFuncAttributeMaxDynamicSharedMemorySize,
                         SMEM_TOTAL);

    convert_init_kernel<<<Dk, 256>>>(imu);
    sim_kernel<<<Nn / 128, 256, SMEM_TOTAL>>>(dbx);
    gather_kernel<<<Bq, Lo / 4>>>(dby, out);
}

// round 11
// speedup vs baseline: 1.9397x; 1.9397x over previous
#include <cuda_runtime.h>
#include <cuda_bf16.h>
#include <cstdint>

#define Bq 256      // queries
#define Dk 768      // feature dim
#define Nn 131072   // database rows
#define Lo 512      // output row length

#define MARGIN 0.2f
#define CAND_CAP 16384
#define NT8 (Nn / 8)           // 16384 8-row groups

// smem: per buffer q 256x144B (36864) + db 128x144B (18432) = 55296
#define F_QH   0
#define F_DH   36864
#define F_BUF  55296
#define SM_INVN 110592         // 128 floats
#define SM_TM   111104         // 256 q x 16 groups u32 = 16384
#define SMEM_TOTAL 127520      // 1 CTA/SM

__device__ __nv_bfloat16 g_qh[Bq * Dk];
__device__ float g_invn[Nn];
__device__ unsigned g_tmax8[(size_t)Bq * NT8];  // per-(q, 8-row group) bf16-sim max
__device__ unsigned long long g_best2[Bq];      // exact argmax keys
__device__ int g_cand_count;
__device__ unsigned g_cand[CAND_CAP];           // (q << 14) | tile8

// ---------------- helpers ----------------
__device__ __forceinline__ uint32_t smem_u32(const void* p) {
    uint32_t a;
    asm("{ .reg .u64 t; cvta.to.shared.u64 t, %1; cvt.u32.u64 %0, t; }"
        : "=r"(a) : "l"(p));
    return a;
}
__device__ __forceinline__ unsigned sortable32(float v) {
    unsigned u = __float_as_uint(v);
    return (u & 0x80000000u) ? ~u : (u | 0x80000000u);
}
__device__ __forceinline__ float unsortable32(unsigned s) {
    unsigned u = (s & 0x80000000u) ? (s & 0x7fffffffu) : ~s;
    return __uint_as_float(u);
}
__device__ __forceinline__ unsigned long long pack_key(float v, unsigned idx) {
    return ((unsigned long long)sortable32(v) << 32) | (unsigned)(~idx);
}
__device__ __forceinline__ uint32_t b2u(__nv_bfloat162 h) {
    return *reinterpret_cast<uint32_t*>(&h);
}
__device__ __forceinline__ void cp_async16(uint32_t dst, const void* src) {
    asm volatile("cp.async.ca.shared.global [%0], [%1], 16;"
                 :: "r"(dst), "l"(src) : "memory");
}
__device__ __forceinline__ void cp_commit() {
    asm volatile("cp.async.commit_group;" ::: "memory");
}
__device__ __forceinline__ void cp_wait_all() {
    asm volatile("cp.async.wait_group 0;" ::: "memory");
}
__device__ __forceinline__ void ldsm_x4(uint32_t* r, uint32_t a) {
    asm volatile("ldmatrix.sync.aligned.m8n8.x4.shared.b16 {%0,%1,%2,%3}, [%4];"
                 : "=r"(r[0]), "=r"(r[1]), "=r"(r[2]), "=r"(r[3]) : "r"(a));
}
__device__ __forceinline__ void mma16816(float* d, const uint32_t* a, const uint32_t* b) {
    asm volatile(
        "mma.sync.aligned.m16n8k16.row.col.f32.bf16.bf16.f32 "
        "{%0,%1,%2,%3},{%4,%5,%6,%7},{%8,%9},{%0,%1,%2,%3};"
        : "+f"(d[0]), "+f"(d[1]), "+f"(d[2]), "+f"(d[3])
        : "r"(a[0]), "r"(a[1]), "r"(a[2]), "r"(a[3]), "r"(b[0]), "r"(b[1]));
}

// ---------------- convert queries + init ----------------
__global__ void convert_init_kernel(const float* __restrict__ x) {
    int i = blockIdx.x * 256 + threadIdx.x;
    g_qh[i] = __float2bfloat16(x[i]);
    if (blockIdx.x == 0) {
        g_best2[threadIdx.x] = 0ull;
        if (threadIdx.x == 0) g_cand_count = 0;
    }
}

// ---------------- pass 1: 1-term bf16 GEMM, 256q x 128n per CTA, db read ONCE ----
__global__ void __launch_bounds__(256, 1) sim_kernel(const float* __restrict__ db) {
    extern __shared__ char smem[];
    const uint32_t sb32 = smem_u32(smem);
    const int tid  = threadIdx.x;
    const int lane = tid & 31;
    const int w    = tid >> 5;
    const int n0   = blockIdx.x * 128;
    const int qb   = (w & 3) * 64;     // 64 queries per warp (4 x m16)
    const int nb   = (w >> 2) * 64;    // 64 db rows per warp
    float* s_invn  = (float*)(smem + SM_INVN);
    unsigned* s_tm = (unsigned*)(smem + SM_TM);   // [256 q][16 groups]

    const int row  = tid >> 1;         // db row 0..127
    const int half = tid & 1;

    float acc[4][8][4];
#pragma unroll
    for (int a = 0; a < 4; a++)
#pragma unroll
        for (int b = 0; b < 8; b++)
#pragma unroll
            for (int r = 0; r < 4; r++) acc[a][b][r] = 0.f;
    float ps = 0.f;

#pragma unroll 1
    for (int c = 0; c < 12; c++) {
        const int bufo = (c & 1) * F_BUF;
        const int k0 = c * 64;
        // ---- q tile (256 rows x 64k bf16) via cp.async: 8 x 16B per thread ----
        {
#pragma unroll
            for (int v = 0; v < 8; v++) {
                int ii  = tid + 256 * v;      // 0..2047
                int qr  = ii >> 3;
                int c16 = ii & 7;
                cp_async16(sb32 + bufo + F_QH + qr * 144 + c16 * 16,
                           g_qh + (size_t)qr * Dk + k0 + c16 * 8);
            }
            cp_commit();
        }
        // ---- db tile (128 rows x 64k): fp32 -> bf16, fuse norms ----
        {
            const float4* dsrc = (const float4*)(db + (size_t)(n0 + row) * Dk + k0 + half * 32);
            char* ph = smem + bufo + F_DH + row * 144 + half * 64;
#pragma unroll
            for (int i = 0; i < 8; i++) {
                float4 f = dsrc[i];
                ps = fmaf(f.x, f.x, fmaf(f.y, f.y, fmaf(f.z, f.z, fmaf(f.w, f.w, ps))));
                __nv_bfloat162 h01 = __floats2bfloat162_rn(f.x, f.y);
                __nv_bfloat162 h23 = __floats2bfloat162_rn(f.z, f.w);
                *(uint2*)(ph + i * 8) = make_uint2(b2u(h01), b2u(h23));
            }
        }
        cp_wait_all();
        __syncthreads();   // single sync per chunk

        const uint32_t sqh = sb32 + bufo + F_QH;
        const uint32_t sdh = sb32 + bufo + F_DH;
#pragma unroll
        for (int ks = 0; ks < 4; ks++) {
            uint32_t aH[4][4];
#pragma unroll
            for (int mi = 0; mi < 4; mi++) {
                uint32_t ao = (uint32_t)((qb + mi * 16 + (lane & 15)) * 144 +
                                         ks * 32 + (lane >> 4) * 16);
                ldsm_x4(aH[mi], sqh + ao);
            }
#pragma unroll
            for (int nip = 0; nip < 4; nip++) {
                uint32_t bo = (uint32_t)((nb + nip * 16 + (lane & 7) +
                                          ((lane >> 4) & 1) * 8) * 144 +
                                         ks * 32 + ((lane >> 3) & 1) * 16);
                uint32_t bh[4];
                ldsm_x4(bh, sdh + bo);
#pragma unroll
                for (int mi = 0; mi < 4; mi++)
#pragma unroll
                    for (int s = 0; s < 2; s++)
                        mma16816(acc[mi][nip * 2 + s], aH[mi], &bh[2 * s]);
            }
        }
        // no trailing sync: buffer reuse at c+2 ordered by sync inside c+1
        // (per-warp program order: MMA(c) precedes stores(c+1) precedes sync(c+1))
    }
    __syncthreads();   // all MMAs done before smem reuse

    // ---- inverse norms for this 128-row tile (db read once -> write once) ----
    {
        float s = ps + __shfl_xor_sync(0xffffffffu, ps, 1);
        if (!half) {
            float r = 1.0f / fmaxf(sqrtf(s), 1e-8f);
            s_invn[row] = r;
            g_invn[n0 + row] = r;
        }
    }
    __syncthreads();

    // ---- per-(q, 8-row group) max -> smem -> coalesced gmem ----
#pragma unroll
    for (int mi = 0; mi < 4; mi++)
#pragma unroll
        for (int g8 = 0; g8 < 2; g8++) {
            const int q = qb + mi * 16 + g8 * 8 + (lane >> 2);
#pragma unroll
            for (int ni = 0; ni < 8; ni++) {
                int nl0 = nb + ni * 8 + (lane & 3) * 2;
                float m = fmaxf(acc[mi][ni][g8 * 2 + 0] * s_invn[nl0],
                                acc[mi][ni][g8 * 2 + 1] * s_invn[nl0 + 1]);
                m = fmaxf(m, __shfl_xor_sync(0xffffffffu, m, 1));
                m = fmaxf(m, __shfl_xor_sync(0xffffffffu, m, 2));
                if ((lane & 3) == 0)
                    s_tm[q * 16 + (nb >> 3) + ni] = sortable32(m);
            }
        }
    __syncthreads();
    {
        // 256 threads x 16 u32 (one q row each), 4x uint4 stores
        uint4* dst = (uint4*)(g_tmax8 + (size_t)tid * NT8 + (n0 >> 3));
        const unsigned* src = s_tm + tid * 16;
#pragma unroll
        for (int i = 0; i < 4; i++)
            dst[i] = make_uint4(src[4 * i], src[4 * i + 1], src[4 * i + 2], src[4 * i + 3]);
    }
}

// ---------------- pass 2: per-query tile8 filter ----------------
__global__ void __launch_bounds__(256) reduce_kernel() {
    const int q = blockIdx.x;
    const int tid = threadIdx.x;
    __shared__ unsigned s_red[256];
    const unsigned* tm = g_tmax8 + (size_t)q * NT8;

    unsigned m = 0;
    unsigned v[64];
#pragma unroll
    for (int i = 0; i < 64; i++) {
        v[i] = tm[tid + 256 * i];
        m = m > v[i] ? m : v[i];
    }
    s_red[tid] = m;
    __syncthreads();
#pragma unroll
    for (int s = 128; s; s >>= 1) {
        if (tid < s) {
            unsigned o = s_red[tid + s];
            if (o > s_red[tid]) s_red[tid] = o;
        }
        __syncthreads();
    }
    const unsigned thr = sortable32(unsortable32(s_red[0]) - MARGIN);
#pragma unroll
    for (int i = 0; i < 64; i++) {
        if (v[i] >= thr) {
            int slot = atomicAdd(&g_cand_count, 1);
            if (slot < CAND_CAP)
                g_cand[slot] = ((unsigned)q << 14) | (unsigned)(tid + 256 * i);
        }
    }
}

// ---------------- pass 3: exact fp32 rescore (one warp per row, 8 rows/cand) ----
__global__ void __launch_bounds__(256) rescore_kernel(const float* __restrict__ x,
                                                      const float* __restrict__ db) {
    __shared__ float xq[Dk];
    const int tid  = threadIdx.x;
    const int lane = tid & 31;
    const int warp = tid >> 5;
    int cnt = g_cand_count;
    if (cnt > CAND_CAP) cnt = CAND_CAP;

    for (int i = blockIdx.x; i < cnt; i += gridDim.x) {
        unsigned c = g_cand[i];
        unsigned q = c >> 14;
        unsigned t = c & 16383u;
        for (int j = tid; j < Dk; j += 256) xq[j] = x[(size_t)q * Dk + j];
        __syncthreads();
        int n = (int)t * 8 + warp;
        const float* d = db + (size_t)n * Dk;
        float s = 0.f;
#pragma unroll
        for (int j = 0; j < 24; j++)
            s = fmaf(xq[j * 32 + lane], d[j * 32 + lane], s);
#pragma unroll
        for (int mm = 16; mm; mm >>= 1) s += __shfl_xor_sync(0xffffffffu, s, mm);
        if (lane == 0)
            atomicMax(&g_best2[q], pack_key(s * g_invn[n], (unsigned)n));
        __syncthreads();
    }
}

// ---------------- gather ----------------
__global__ void gather_kernel(const float* __restrict__ y, float* __restrict__ out) {
    const int b = blockIdx.x;
    unsigned idx = ~((unsigned)(g_best2[b] & 0xffffffffull));
    const float4* src = (const float4*)(y + (size_t)idx * Lo);
    float4* dst = (float4*)(out + (size_t)b * Lo);
    dst[threadIdx.x] = src[threadIdx.x];
}

extern "C" void kernel_launch(void* const* d_in, const int* in_sizes, int n_in,
                              void* d_out, int out_size) {
    const float* imu = (const float*)d_in[0];
    const float* dbx = (const float*)d_in[1];
    const float* dby = (const float*)d_in[2];
    float* out = (float*)d_out;

    cudaFuncSetAttribute(sim_kernel, cudaFuncAttributeMaxDynamicSharedMemorySize,
                         SMEM_TOTAL);

    convert_init_kernel<<<Dk, 256>>>(imu);
    sim_kernel<<<Nn / 128, 256, SMEM_TOTAL>>>(dbx);
    reduce_kernel<<<Bq, 256>>>();
    rescore_kernel<<<512, 256>>>(imu, dbx);
    gather_kernel<<<Bq, Lo / 4>>>(dby, out);
}

// round 12
// speedup vs baseline: 2.3564x; 1.2148x over previous
#include <cuda_runtime.h>
#include <cuda_bf16.h>
#include <cstdint>

#define Bq 256      // queries
#define Dk 768      // feature dim
#define Nn 131072   // database rows
#define Lo 512      // output row length

#define MARGIN 0.2f
#define CAND_CAP 16384
#define NT8 (Nn / 8)           // 16384 8-row groups

// smem: per buffer q 256x144B (36864) + db 64x144B (9216) = 46080
#define F_QH   0
#define F_DH   36864
#define F_BUF  46080
#define SM_INVN 92160          // 64 floats
#define SM_TM   92448          // 256 q x 8 groups u32 = 8192
#define SMEM_TOTAL 100672      // x2 CTAs = 201344 < 227KB -> 2 CTAs/SM

__device__ __nv_bfloat16 g_qh[Bq * Dk];
__device__ float g_invn[Nn];
__device__ unsigned g_tmax8[(size_t)Bq * NT8];  // per-(q, 8-row group) bf16-sim max
__device__ unsigned long long g_best2[Bq];      // exact argmax keys
__device__ int g_cand_count;
__device__ unsigned g_cand[CAND_CAP];           // (q << 14) | tile8

// ---------------- helpers ----------------
__device__ __forceinline__ uint32_t smem_u32(const void* p) {
    uint32_t a;
    asm("{ .reg .u64 t; cvta.to.shared.u64 t, %1; cvt.u32.u64 %0, t; }"
        : "=r"(a) : "l"(p));
    return a;
}
__device__ __forceinline__ unsigned sortable32(float v) {
    unsigned u = __float_as_uint(v);
    return (u & 0x80000000u) ? ~u : (u | 0x80000000u);
}
__device__ __forceinline__ float unsortable32(unsigned s) {
    unsigned u = (s & 0x80000000u) ? (s & 0x7fffffffu) : ~s;
    return __uint_as_float(u);
}
__device__ __forceinline__ unsigned long long pack_key(float v, unsigned idx) {
    return ((unsigned long long)sortable32(v) << 32) | (unsigned)(~idx);
}
__device__ __forceinline__ uint32_t b2u(__nv_bfloat162 h) {
    return *reinterpret_cast<uint32_t*>(&h);
}
__device__ __forceinline__ void cp_async16(uint32_t dst, const void* src) {
    asm volatile("cp.async.ca.shared.global [%0], [%1], 16;"
                 :: "r"(dst), "l"(src) : "memory");
}
__device__ __forceinline__ void cp_commit() {
    asm volatile("cp.async.commit_group;" ::: "memory");
}
__device__ __forceinline__ void cp_wait_all() {
    asm volatile("cp.async.wait_group 0;" ::: "memory");
}
__device__ __forceinline__ void ldsm_x4(uint32_t* r, uint32_t a) {
    asm volatile("ldmatrix.sync.aligned.m8n8.x4.shared.b16 {%0,%1,%2,%3}, [%4];"
                 : "=r"(r[0]), "=r"(r[1]), "=r"(r[2]), "=r"(r[3]) : "r"(a));
}
__device__ __forceinline__ void mma16816(float* d, const uint32_t* a, const uint32_t* b) {
    asm volatile(
        "mma.sync.aligned.m16n8k16.row.col.f32.bf16.bf16.f32 "
        "{%0,%1,%2,%3},{%4,%5,%6,%7},{%8,%9},{%0,%1,%2,%3};"
        : "+f"(d[0]), "+f"(d[1]), "+f"(d[2]), "+f"(d[3])
        : "r"(a[0]), "r"(a[1]), "r"(a[2]), "r"(a[3]), "r"(b[0]), "r"(b[1]));
}

// ---------------- convert queries + init ----------------
__global__ void convert_init_kernel(const float* __restrict__ x) {
    int i = blockIdx.x * 256 + threadIdx.x;
    g_qh[i] = __float2bfloat16(x[i]);
    if (blockIdx.x == 0) {
        g_best2[threadIdx.x] = 0ull;
        if (threadIdx.x == 0) g_cand_count = 0;
    }
}

// ---------------- pass 1: 1-term bf16 GEMM, 256q x 64n per CTA, db read ONCE ----
__global__ void __launch_bounds__(256, 2) sim_kernel(const float* __restrict__ db) {
    extern __shared__ char smem[];
    const uint32_t sb32 = smem_u32(smem);
    const int tid  = threadIdx.x;
    const int lane = tid & 31;
    const int w    = tid >> 5;
    const int n0   = blockIdx.x * 64;
    const int qb   = (w & 3) * 64;     // 64 queries per warp (4 x m16)
    const int nb   = (w >> 2) * 32;    // 32 db rows per warp (2 x n16)
    float* s_invn  = (float*)(smem + SM_INVN);
    unsigned* s_tm = (unsigned*)(smem + SM_TM);   // [256 q][8 groups]

    const int row = tid >> 2;          // db row 0..63
    const int kq  = tid & 3;           // 16-float slice within the 64-k chunk

    float acc[4][4][4];
#pragma unroll
    for (int a = 0; a < 4; a++)
#pragma unroll
        for (int b = 0; b < 4; b++)
#pragma unroll
            for (int r = 0; r < 4; r++) acc[a][b][r] = 0.f;
    float ps = 0.f;

#pragma unroll 1
    for (int c = 0; c < 12; c++) {
        const int bufo = (c & 1) * F_BUF;
        const int k0 = c * 64;
        // ---- q tile (256 rows x 64k bf16) via cp.async: 8 x 16B per thread ----
        {
#pragma unroll
            for (int v = 0; v < 8; v++) {
                int ii  = tid + 256 * v;      // 0..2047
                int qr  = ii >> 3;
                int c16 = ii & 7;
                cp_async16(sb32 + bufo + F_QH + qr * 144 + c16 * 16,
                           g_qh + (size_t)qr * Dk + k0 + c16 * 8);
            }
            cp_commit();
        }
        // ---- db tile (64 rows x 64k): fp32 -> bf16, fuse norms; 4 LDG.128/thread ----
        {
            const float4* dsrc = (const float4*)(db + (size_t)(n0 + row) * Dk + k0 + kq * 16);
            float4 f0 = dsrc[0], f1 = dsrc[1], f2 = dsrc[2], f3 = dsrc[3];
            ps = fmaf(f0.x, f0.x, fmaf(f0.y, f0.y, fmaf(f0.z, f0.z, fmaf(f0.w, f0.w, ps))));
            ps = fmaf(f1.x, f1.x, fmaf(f1.y, f1.y, fmaf(f1.z, f1.z, fmaf(f1.w, f1.w, ps))));
            ps = fmaf(f2.x, f2.x, fmaf(f2.y, f2.y, fmaf(f2.z, f2.z, fmaf(f2.w, f2.w, ps))));
            ps = fmaf(f3.x, f3.x, fmaf(f3.y, f3.y, fmaf(f3.z, f3.z, fmaf(f3.w, f3.w, ps))));
            char* ph = smem + bufo + F_DH + row * 144 + kq * 32;
            *(uint4*)(ph) = make_uint4(
                b2u(__floats2bfloat162_rn(f0.x, f0.y)), b2u(__floats2bfloat162_rn(f0.z, f0.w)),
                b2u(__floats2bfloat162_rn(f1.x, f1.y)), b2u(__floats2bfloat162_rn(f1.z, f1.w)));
            *(uint4*)(ph + 16) = make_uint4(
                b2u(__floats2bfloat162_rn(f2.x, f2.y)), b2u(__floats2bfloat162_rn(f2.z, f2.w)),
                b2u(__floats2bfloat162_rn(f3.x, f3.y)), b2u(__floats2bfloat162_rn(f3.z, f3.w)));
        }
        cp_wait_all();
        __syncthreads();   // single sync per chunk

        const uint32_t sqh = sb32 + bufo + F_QH;
        const uint32_t sdh = sb32 + bufo + F_DH;
#pragma unroll
        for (int ks = 0; ks < 4; ks++) {
            uint32_t aH[4][4];
#pragma unroll
            for (int mi = 0; mi < 4; mi++) {
                uint32_t ao = (uint32_t)((qb + mi * 16 + (lane & 15)) * 144 +
                                         ks * 32 + (lane >> 4) * 16);
                ldsm_x4(aH[mi], sqh + ao);
            }
#pragma unroll
            for (int nip = 0; nip < 2; nip++) {
                uint32_t bo = (uint32_t)((nb + nip * 16 + (lane & 7) +
                                          ((lane >> 4) & 1) * 8) * 144 +
                                         ks * 32 + ((lane >> 3) & 1) * 16);
                uint32_t bh[4];
                ldsm_x4(bh, sdh + bo);
#pragma unroll
                for (int mi = 0; mi < 4; mi++)
#pragma unroll
                    for (int s = 0; s < 2; s++)
                        mma16816(acc[mi][nip * 2 + s], aH[mi], &bh[2 * s]);
            }
        }
        // no trailing sync: buffer reuse at c+2 ordered by the sync inside c+1
    }
    __syncthreads();   // all MMAs done before smem reuse

    // ---- inverse norms: 4 lanes (kq) share a row ----
    {
        float s = ps;
        s += __shfl_xor_sync(0xffffffffu, s, 1);
        s += __shfl_xor_sync(0xffffffffu, s, 2);
        if (kq == 0) {
            float r = 1.0f / fmaxf(sqrtf(s), 1e-8f);
            s_invn[row] = r;
            g_invn[n0 + row] = r;     // each db row owned by exactly one CTA
        }
    }
    __syncthreads();

    // ---- per-(q, 8-row group) max -> smem ----
    // acc[mi][j]: q rows qb+mi*16+(lane>>2) (+8 for regs 2,3); n cols nb+j*8+(lane&3)*2+{0,1}
#pragma unroll
    for (int mi = 0; mi < 4; mi++)
#pragma unroll
        for (int j = 0; j < 4; j++) {
            int nl0 = nb + j * 8 + (lane & 3) * 2;
            float i0 = s_invn[nl0], i1 = s_invn[nl0 + 1];
            float m0 = fmaxf(acc[mi][j][0] * i0, acc[mi][j][1] * i1);
            float m1 = fmaxf(acc[mi][j][2] * i0, acc[mi][j][3] * i1);
            m0 = fmaxf(m0, __shfl_xor_sync(0xffffffffu, m0, 1));
            m0 = fmaxf(m0, __shfl_xor_sync(0xffffffffu, m0, 2));
            m1 = fmaxf(m1, __shfl_xor_sync(0xffffffffu, m1, 1));
            m1 = fmaxf(m1, __shfl_xor_sync(0xffffffffu, m1, 2));
            if ((lane & 3) == 0) {
                int g = (nb >> 3) + j;
                s_tm[(qb + mi * 16 + (lane >> 2)) * 8 + g]     = sortable32(m0);
                s_tm[(qb + mi * 16 + (lane >> 2) + 8) * 8 + g] = sortable32(m1);
            }
        }
    __syncthreads();
    // ---- coalesced write: thread tid owns q row tid, 8 u32 ----
    {
        uint4* dst = (uint4*)(g_tmax8 + (size_t)tid * NT8 + (n0 >> 3));
        const unsigned* src = s_tm + tid * 8;
        dst[0] = make_uint4(src[0], src[1], src[2], src[3]);
        dst[1] = make_uint4(src[4], src[5], src[6], src[7]);
    }
}

// ---------------- pass 2: per-query tile8 filter ----------------
__global__ void __launch_bounds__(256) reduce_kernel() {
    const int q = blockIdx.x;
    const int tid = threadIdx.x;
    __shared__ unsigned s_red[256];
    const unsigned* tm = g_tmax8 + (size_t)q * NT8;

    unsigned m = 0;
    unsigned v[64];
#pragma unroll
    for (int i = 0; i < 64; i++) {
        v[i] = tm[tid + 256 * i];
        m = m > v[i] ? m : v[i];
    }
    s_red[tid] = m;
    __syncthreads();
#pragma unroll
    for (int s = 128; s; s >>= 1) {
        if (tid < s) {
            unsigned o = s_red[tid + s];
            if (o > s_red[tid]) s_red[tid] = o;
        }
        __syncthreads();
    }
    const unsigned thr = sortable32(unsortable32(s_red[0]) - MARGIN);
#pragma unroll
    for (int i = 0; i < 64; i++) {
        if (v[i] >= thr) {
            int slot = atomicAdd(&g_cand_count, 1);
            if (slot < CAND_CAP)
                g_cand[slot] = ((unsigned)q << 14) | (unsigned)(tid + 256 * i);
        }
    }
}

// ---------------- pass 3: exact fp32 rescore (one warp per row, 8 rows/cand) ----
__global__ void __launch_bounds__(256) rescore_kernel(const float* __restrict__ x,
                                                      const float* __restrict__ db) {
    __shared__ float xq[Dk];
    const int tid  = threadIdx.x;
    const int lane = tid & 31;
    const int warp = tid >> 5;
    int cnt = g_cand_count;
    if (cnt > CAND_CAP) cnt = CAND_CAP;

    for (int i = blockIdx.x; i < cnt; i += gridDim.x) {
        unsigned c = g_cand[i];
        unsigned q = c >> 14;
        unsigned t = c & 16383u;
        for (int j = tid; j < Dk; j += 256) xq[j] = x[(size_t)q * Dk + j];
        __syncthreads();
        int n = (int)t * 8 + warp;
        const float* d = db + (size_t)n * Dk;
        float s = 0.f;
#pragma unroll
        for (int j = 0; j < 24; j++)
            s = fmaf(xq[j * 32 + lane], d[j * 32 + lane], s);
#pragma unroll
        for (int mm = 16; mm; mm >>= 1) s += __shfl_xor_sync(0xffffffffu, s, mm);
        if (lane == 0)
            atomicMax(&g_best2[q], pack_key(s * g_invn[n], (unsigned)n));
        __syncthreads();
    }
}

// ---------------- gather ----------------
__global__ void gather_kernel(const float* __restrict__ y, float* __restrict__ out) {
    const int b = blockIdx.x;
    unsigned idx = ~((unsigned)(g_best2[b] & 0xffffffffull));
    const float4* src = (const float4*)(y + (size_t)idx * Lo);
    float4* dst = (float4*)(out + (size_t)b * Lo);
    dst[threadIdx.x] = src[threadIdx.x];
}

extern "C" void kernel_launch(void* const* d_in, const int* in_sizes, int n_in,
                              void* d_out, int out_size) {
    const float* imu = (const float*)d_in[0];
    const float* dbx = (const float*)d_in[1];
    const float* dby = (const float*)d_in[2];
    float* out = (float*)d_out;

    cudaFuncSetAttribute(sim_kernel, cudaFuncAttributeMaxDynamicSharedMemorySize,
                         SMEM_TOTAL);

    convert_init_kernel<<<Dk, 256>>>(imu);
    sim_kernel<<<Nn / 64, 256, SMEM_TOTAL>>>(dbx);
    reduce_kernel<<<Bq, 256>>>();
    rescore_kernel<<<512, 256>>>(imu, dbx);
    gather_kernel<<<Bq, Lo / 4>>>(dby, out);
}